// round 14
// baseline (speedup 1.0000x reference)
#include <cuda_runtime.h>
#include <cuda_bf16.h>
#include <math.h>
#include <stdint.h>

#define B_  8
#define L_  2048
#define E_  100
#define FM_ 50
#define Y_  8921
#define K_  9

#define YT    32          // labels per attn block
#define NYT   279         // ceil(Y_/YT)
#define FPAIR 28          // bf16-pair row stride (24 real pairs + 4 pad)
#define LCH   256         // positions per chunk
#define NCHK  (L_ / LCH)  // 8
#define NKB   3           // k-steps of 16 covering f 0..47; f 48,49 via fp32 fixup
#define LOG2E 1.4426950408889634f

// scratch (static device arrays are allowed)
__device__ uint32_t g_hhi[(size_t)B_ * L_ * FPAIR];   // bf16 hi pairs [b][l][28]
__device__ uint32_t g_hlo[(size_t)B_ * L_ * FPAIR];   // bf16 lo pairs
__device__ float    g_h2 [(size_t)B_ * L_ * 2];       // fp32 h for f=48,49
__device__ float    g_losspart[B_ * NYT];

// ---- bf16 helpers ----------------------------------------------------------
__device__ __forceinline__ uint32_t pack_bf2(__nv_bfloat16 a, __nv_bfloat16 b) {
    return (uint32_t)__bfloat16_as_ushort(a) |
           ((uint32_t)__bfloat16_as_ushort(b) << 16);
}
__device__ __forceinline__ void split_bf(float x, __nv_bfloat16& h, __nv_bfloat16& l) {
    h = __float2bfloat16(x);
    l = __float2bfloat16(x - __bfloat162float(h));
}
__device__ __forceinline__ void mma_bf16(float d[4], const uint32_t a[4],
                                         uint32_t b0, uint32_t b1) {
    asm("mma.sync.aligned.m16n8k16.row.col.f32.bf16.bf16.f32 "
        "{%0,%1,%2,%3},{%4,%5,%6,%7},{%8,%9},{%0,%1,%2,%3};"
        : "+f"(d[0]), "+f"(d[1]), "+f"(d[2]), "+f"(d[3])
        : "r"(a[0]), "r"(a[1]), "r"(a[2]), "r"(a[3]), "r"(b0), "r"(b1));
}

// ---------------------------------------------------------------------------
// Kernel 1: embed + conv1d(K=9) + bias + tanh.
// f 0..47 -> bf16 hi/lo pair planes; f 48,49 -> fp32 g_h2. (unchanged, proven)
// ---------------------------------------------------------------------------
__global__ void __launch_bounds__(256) conv_kernel(
    const int* __restrict__ tokens,
    const float* __restrict__ embed_W,
    const float* __restrict__ conv_w,
    const float* __restrict__ conv_b)
{
    __shared__ int   tok_s[72];
    __shared__ float x_s[72][21];
    __shared__ float w_s[50][20][9];

    const int tid   = threadIdx.x;
    const int b     = blockIdx.y;
    const int lbase = blockIdx.x * 64;

    if (tid < 72) {
        int gl = lbase + tid - 4;
        tok_s[tid] = (gl >= 0 && gl < L_) ? tokens[b * L_ + gl] : -1;
    }
    __syncthreads();

    const int f  = tid >> 2;
    const int lg = tid & 3;
    const int l0 = lg * 16;

    float acc[16];
#pragma unroll
    for (int j = 0; j < 16; j++) acc[j] = 0.f;

    for (int ec = 0; ec < 5; ec++) {
        for (int idx = tid; idx < 72 * 20; idx += 256) {
            int i = idx / 20, e = idx % 20;
            int t = tok_s[i];
            x_s[i][e] = (t >= 0) ? embed_W[(size_t)t * E_ + ec * 20 + e] : 0.f;
        }
        for (int idx = tid; idx < 50 * 20 * 9; idx += 256) {
            int ff = idx / 180, r = idx % 180;
            w_s[ff][r / 9][r % 9] = conv_w[ff * (E_ * K_) + ec * 180 + r];
        }
        __syncthreads();

        if (f < FM_) {
            for (int e = 0; e < 20; e++) {
                float xv[24];
#pragma unroll
                for (int t = 0; t < 24; t++) xv[t] = x_s[l0 + t][e];
                float wv[9];
#pragma unroll
                for (int k = 0; k < 9; k++) wv[k] = w_s[f][e][k];
#pragma unroll
                for (int k = 0; k < 9; k++)
#pragma unroll
                    for (int j = 0; j < 16; j++)
                        acc[j] += xv[j + k] * wv[k];
            }
        }
        __syncthreads();
    }

    if (f < FM_) {
        const float bias = conv_b[f];
        unsigned short* phi = (unsigned short*)g_hhi;
        unsigned short* plo = (unsigned short*)g_hlo;
#pragma unroll
        for (int j = 0; j < 16; j++) {
            int l = lbase + l0 + j;
            float v = tanhf(acc[j] + bias);
            if (f < 48) {
                __nv_bfloat16 hb, lb;
                split_bf(v, hb, lb);
                size_t o = ((size_t)b * L_ + l) * (2 * FPAIR) + f;
                phi[o] = __bfloat16_as_ushort(hb);
                plo[o] = __bfloat16_as_ushort(lb);
            } else {
                g_h2[((size_t)b * L_ + l) * 2 + (f - 48)] = v;
            }
        }
    }
}

// ---------------------------------------------------------------------------
// Kernel 2: two-phase label attention. 256 threads, 2 CTAs/SM.
// Phase 1: S (3-term bf16 mma) + Q (1-term bf16 mma) + fp32 fixup, accumulate
//          Z, R. NO gmem writes.
// Reduce:  iZ per label, yhat, loss.
// Phase 2: restage h, recompute S with the bit-identical mma/fixup sequence,
//          write alpha = exp2(s) * iZ directly (single normalized write).
// ---------------------------------------------------------------------------
__global__ void __launch_bounds__(256, 2) attn_kernel(
    const float* __restrict__ U_w,
    const float* __restrict__ final_w,
    const float* __restrict__ final_b,
    const float* __restrict__ target,
    float* __restrict__ out_yhat,
    float* __restrict__ out_alpha,
    int write_alpha)
{
    extern __shared__ __align__(16) unsigned char smraw[];
    uint4*    wS   = (uint4*)smraw;                    // [NKB*4*32] 6144 B
    uint2*    wQ   = (uint2*)(wS + NKB * 4 * 32);      // hi-only    3072 B
    uint32_t* smhi = (uint32_t*)(wQ + NKB * 4 * 32);   // [LCH*FPAIR] 28672 B
    uint32_t* smlo = smhi + LCH * FPAIR;               // 28672 B
    float*    h2s  = (float*)(smlo + LCH * FPAIR);     // [LCH*2] 2048 B
    float4*   w2s  = (float4*)(h2s + LCH * 2);         // [32] 512 B
    float*    zs   = (float*)(w2s + 32);               // [8*32]
    float*    rs   = zs + 8 * 32;                      // [8*32]
    float*    iZ_s = rs + 8 * 32;                      // [32]
    float*    lt   = iZ_s + YT;                        // [32]

    const int tid  = threadIdx.x;
    const int lane = tid & 31;
    const int warp = tid >> 5;
    const int b    = blockIdx.y;
    const int y0t  = blockIdx.x * YT;

    const int g = lane >> 2;       // mma groupID (0..7)
    const int t = lane & 3;        // mma thread-in-group (0..3)

    // ---- fragment-order weights: S hi/lo (U pre-scaled by log2e), Q hi only
    for (int idx = tid; idx < NKB * 4 * 32; idx += 256) {
        int k  = idx >> 7;
        int nt = (idx >> 5) & 3;
        int ln = idx & 31;
        int gg = ln >> 2, tt = ln & 3;
        int gy = y0t + nt * 8 + gg;
        int f00 = k * 16 + 2 * tt, f01 = f00 + 1;
        int f10 = f00 + 8,         f11 = f10 + 1;
        float u00=0.f,u01=0.f,u10=0.f,u11=0.f, v00=0.f,v01=0.f,v10=0.f,v11=0.f;
        if (gy < Y_) {
            const float* up = U_w     + gy * FM_;
            const float* vp = final_w + gy * FM_;
            u00 = up[f00] * LOG2E; v00 = vp[f00];
            u01 = up[f01] * LOG2E; v01 = vp[f01];
            u10 = up[f10] * LOG2E; v10 = vp[f10];
            u11 = up[f11] * LOG2E; v11 = vp[f11];
        }
        __nv_bfloat16 h00,l00,h01,l01,h10,l10,h11,l11;
        split_bf(u00,h00,l00); split_bf(u01,h01,l01);
        split_bf(u10,h10,l10); split_bf(u11,h11,l11);
        wS[idx] = make_uint4(pack_bf2(h00,h01), pack_bf2(h10,h11),
                             pack_bf2(l00,l01), pack_bf2(l10,l11));
        wQ[idx] = make_uint2(pack_bf2(__float2bfloat16(v00), __float2bfloat16(v01)),
                             pack_bf2(__float2bfloat16(v10), __float2bfloat16(v11)));
    }
    // fp32 fixup weights for f=48,49
    if (tid < YT) {
        int gy = y0t + tid;
        float4 w = make_float4(0.f, 0.f, 0.f, 0.f);
        if (gy < Y_) {
            w.x = U_w[gy * FM_ + 48] * LOG2E;
            w.y = U_w[gy * FM_ + 49] * LOG2E;
            w.z = final_w[gy * FM_ + 48];
            w.w = final_w[gy * FM_ + 49];
        }
        w2s[tid] = w;
    }

    float Zl[4][2] = {{0.f,0.f},{0.f,0.f},{0.f,0.f},{0.f,0.f}};
    float Rl[4][2] = {{0.f,0.f},{0.f,0.f},{0.f,0.f},{0.f,0.f}};

    const size_t arow0 = (size_t)b * Y_;
    const int prow0 = warp * 32;

    // staging helper (macro so both phases share the exact code)
#define STAGE_CHUNK(ch) do {                                                 \
        const uint4* shi = (const uint4*)(g_hhi +                            \
            ((size_t)b * L_ + (size_t)(ch) * LCH) * FPAIR);                  \
        const uint4* slo = (const uint4*)(g_hlo +                            \
            ((size_t)b * L_ + (size_t)(ch) * LCH) * FPAIR);                  \
        uint4* dhi = (uint4*)smhi;                                           \
        uint4* dlo = (uint4*)smlo;                                           \
        for (int i = tid; i < LCH * FPAIR / 4; i += 256) {                   \
            dhi[i] = shi[i];                                                 \
            dlo[i] = slo[i];                                                 \
        }                                                                    \
        const float4* sh2 = (const float4*)(g_h2 +                           \
            ((size_t)b * L_ + (size_t)(ch) * LCH) * 2);                      \
        if (tid < LCH * 2 / 4) ((float4*)h2s)[tid] = sh2[tid];               \
    } while (0)

    // load A fragments for (k, mt) — identical in both phases
#define LOAD_A(k)                                                            \
        uint32_t ahi[2][4], alo[2][4];                                       \
        _Pragma("unroll")                                                    \
        for (int mt = 0; mt < 2; mt++) {                                     \
            const int r0 = prow0 + mt * 16;                                  \
            const int pa = (k) * 8 + t;                                      \
            ahi[mt][0] = smhi[(r0 + g)     * FPAIR + pa];                    \
            ahi[mt][1] = smhi[(r0 + g + 8) * FPAIR + pa];                    \
            ahi[mt][2] = smhi[(r0 + g)     * FPAIR + pa + 4];                \
            ahi[mt][3] = smhi[(r0 + g + 8) * FPAIR + pa + 4];                \
            alo[mt][0] = smlo[(r0 + g)     * FPAIR + pa];                    \
            alo[mt][1] = smlo[(r0 + g + 8) * FPAIR + pa];                    \
            alo[mt][2] = smlo[(r0 + g)     * FPAIR + pa + 4];                \
            alo[mt][3] = smlo[(r0 + g + 8) * FPAIR + pa + 4];                \
        }

    // ---------------- phase 1: Z, R (no gmem writes) ----------------
    for (int ch = 0; ch < NCHK; ch++) {
        __syncthreads();
        STAGE_CHUNK(ch);
        __syncthreads();

        float accS[2][4][4] = {};
        float accQ[2][4][4] = {};

#pragma unroll
        for (int k = 0; k < NKB; k++) {
            LOAD_A(k);
#pragma unroll
            for (int nt = 0; nt < 4; nt++) {
                uint4 Bs = wS[(k * 4 + nt) * 32 + lane];
                uint2 Bq = wQ[(k * 4 + nt) * 32 + lane];
#pragma unroll
                for (int mt = 0; mt < 2; mt++) {
                    mma_bf16(accS[mt][nt], ahi[mt], Bs.x, Bs.y);  // ah*bh
                    mma_bf16(accS[mt][nt], ahi[mt], Bs.z, Bs.w);  // ah*bl
                    mma_bf16(accS[mt][nt], alo[mt], Bs.x, Bs.y);  // al*bh
                    mma_bf16(accQ[mt][nt], ahi[mt], Bq.x, Bq.y);  // Q 1-term
                }
            }
        }

        // fp32 fixup (f=48,49) — S and Q
#pragma unroll
        for (int mt = 0; mt < 2; mt++) {
            const int pA = prow0 + mt * 16 + g;
            float hA0 = h2s[pA * 2],       hA1 = h2s[pA * 2 + 1];
            float hB0 = h2s[(pA + 8) * 2], hB1 = h2s[(pA + 8) * 2 + 1];
#pragma unroll
            for (int nt = 0; nt < 4; nt++) {
                float4 wa = w2s[nt * 8 + 2 * t];
                float4 wb = w2s[nt * 8 + 2 * t + 1];
                accS[mt][nt][0] += hA0 * wa.x + hA1 * wa.y;
                accS[mt][nt][1] += hA0 * wb.x + hA1 * wb.y;
                accS[mt][nt][2] += hB0 * wa.x + hB1 * wa.y;
                accS[mt][nt][3] += hB0 * wb.x + hB1 * wb.y;
                accQ[mt][nt][0] += hA0 * wa.z + hA1 * wa.w;
                accQ[mt][nt][1] += hA0 * wb.z + hA1 * wb.w;
                accQ[mt][nt][2] += hB0 * wa.z + hB1 * wa.w;
                accQ[mt][nt][3] += hB0 * wb.z + hB1 * wb.w;
            }
        }

#pragma unroll
        for (int mt = 0; mt < 2; mt++) {
#pragma unroll
            for (int nt = 0; nt < 4; nt++) {
                float e0 = exp2f(accS[mt][nt][0]);
                float e1 = exp2f(accS[mt][nt][1]);
                float e2 = exp2f(accS[mt][nt][2]);
                float e3 = exp2f(accS[mt][nt][3]);
                Zl[nt][0] += e0 + e2;
                Zl[nt][1] += e1 + e3;
                Rl[nt][0] += e0 * accQ[mt][nt][0] + e2 * accQ[mt][nt][2];
                Rl[nt][1] += e1 * accQ[mt][nt][1] + e3 * accQ[mt][nt][3];
            }
        }
    }

    // ---------------- reduce, yhat, loss ----------------
#pragma unroll
    for (int o = 4; o <= 16; o <<= 1) {
#pragma unroll
        for (int nt = 0; nt < 4; nt++) {
            Zl[nt][0] += __shfl_xor_sync(0xffffffffu, Zl[nt][0], o);
            Zl[nt][1] += __shfl_xor_sync(0xffffffffu, Zl[nt][1], o);
            Rl[nt][0] += __shfl_xor_sync(0xffffffffu, Rl[nt][0], o);
            Rl[nt][1] += __shfl_xor_sync(0xffffffffu, Rl[nt][1], o);
        }
    }
    if (lane < 4) {
#pragma unroll
        for (int nt = 0; nt < 4; nt++) {
            zs[warp * 32 + nt * 8 + 2 * lane + 0] = Zl[nt][0];
            zs[warp * 32 + nt * 8 + 2 * lane + 1] = Zl[nt][1];
            rs[warp * 32 + nt * 8 + 2 * lane + 0] = Rl[nt][0];
            rs[warp * 32 + nt * 8 + 2 * lane + 1] = Rl[nt][1];
        }
    }
    __syncthreads();

    if (tid < YT) {
        float Z = 0.f, R = 0.f;
#pragma unroll
        for (int w = 0; w < 8; w++) { Z += zs[w * 32 + tid]; R += rs[w * 32 + tid]; }
        iZ_s[tid] = 1.f / Z;
        float lossterm = 0.f;
        int gy = y0t + tid;
        if (gy < Y_) {
            float r  = R / Z + final_b[gy];
            float yh = 1.f / (1.f + expf(-r));
            out_yhat[b * Y_ + gy] = yh;
            float tg = target[b * Y_ + gy];
            lossterm = tg * logf(yh + 1e-12f) + (1.f - tg) * logf(1.f - yh + 1e-12f);
        }
        lt[tid] = lossterm;
    }
    __syncthreads();
    if (tid == 0) {
        float s = 0.f;
#pragma unroll
        for (int i = 0; i < YT; i++) s += lt[i];
        g_losspart[b * gridDim.x + blockIdx.x] = s;
    }

    if (!write_alpha) return;

    // per-lane iZ for the labels this lane's accumulators map to
    float iZa[4], iZb[4];
#pragma unroll
    for (int nt = 0; nt < 4; nt++) {
        iZa[nt] = iZ_s[nt * 8 + 2 * t];
        iZb[nt] = iZ_s[nt * 8 + 2 * t + 1];
    }

    // ---------------- phase 2: recompute S, write alpha = e * iZ ----------
    for (int ch = 0; ch < NCHK; ch++) {
        __syncthreads();
        STAGE_CHUNK(ch);
        __syncthreads();

        float accS[2][4][4] = {};

#pragma unroll
        for (int k = 0; k < NKB; k++) {
            LOAD_A(k);
#pragma unroll
            for (int nt = 0; nt < 4; nt++) {
                uint4 Bs = wS[(k * 4 + nt) * 32 + lane];
#pragma unroll
                for (int mt = 0; mt < 2; mt++) {
                    mma_bf16(accS[mt][nt], ahi[mt], Bs.x, Bs.y);
                    mma_bf16(accS[mt][nt], ahi[mt], Bs.z, Bs.w);
                    mma_bf16(accS[mt][nt], alo[mt], Bs.x, Bs.y);
                }
            }
        }

#pragma unroll
        for (int mt = 0; mt < 2; mt++) {
            const int pA = prow0 + mt * 16 + g;
            float hA0 = h2s[pA * 2],       hA1 = h2s[pA * 2 + 1];
            float hB0 = h2s[(pA + 8) * 2], hB1 = h2s[(pA + 8) * 2 + 1];
#pragma unroll
            for (int nt = 0; nt < 4; nt++) {
                float4 wa = w2s[nt * 8 + 2 * t];
                float4 wb = w2s[nt * 8 + 2 * t + 1];
                accS[mt][nt][0] += hA0 * wa.x + hA1 * wa.y;
                accS[mt][nt][1] += hA0 * wb.x + hA1 * wb.y;
                accS[mt][nt][2] += hB0 * wa.x + hB1 * wa.y;
                accS[mt][nt][3] += hB0 * wb.x + hB1 * wb.y;
            }
        }

        const int chb = ch * LCH;
#pragma unroll
        for (int mt = 0; mt < 2; mt++) {
            const int posA = chb + prow0 + mt * 16 + g;
            const int posB = posA + 8;
#pragma unroll
            for (int nt = 0; nt < 4; nt++) {
                const int lab0 = y0t + nt * 8 + 2 * t;
                const int lab1 = lab0 + 1;
                float a0 = exp2f(accS[mt][nt][0]) * iZa[nt];
                float a1 = exp2f(accS[mt][nt][1]) * iZb[nt];
                float a2 = exp2f(accS[mt][nt][2]) * iZa[nt];
                float a3 = exp2f(accS[mt][nt][3]) * iZb[nt];
                if (lab0 < Y_) {
                    float* rp = out_alpha + (arow0 + lab0) * L_;
                    rp[posA] = a0; rp[posB] = a2;
                }
                if (lab1 < Y_) {
                    float* rp = out_alpha + (arow0 + lab1) * L_;
                    rp[posA] = a1; rp[posB] = a3;
                }
            }
        }
    }
#undef STAGE_CHUNK
#undef LOAD_A
}

// ---------------------------------------------------------------------------
// Kernel 3: deterministic loss reduction
// ---------------------------------------------------------------------------
__global__ void loss_kernel(float* __restrict__ out_loss, int npart)
{
    __shared__ float red[256];
    float s = 0.f;
    for (int i = threadIdx.x; i < npart; i += 256) s += g_losspart[i];
    red[threadIdx.x] = s;
    __syncthreads();
    for (int o = 128; o > 0; o >>= 1) {
        if (threadIdx.x < o) red[threadIdx.x] += red[threadIdx.x + o];
        __syncthreads();
    }
    if (threadIdx.x == 0) *out_loss = -red[0] / (float)(B_ * Y_);
}

// ---------------------------------------------------------------------------
extern "C" void kernel_launch(void* const* d_in, const int* in_sizes, int n_in,
                              void* d_out, int out_size)
{
    const int*   tokens  = (const int*)  d_in[0];
    const float* target  = (const float*)d_in[1];
    const float* embed_W = (const float*)d_in[2];
    const float* conv_w  = (const float*)d_in[3];
    const float* conv_b  = (const float*)d_in[4];
    const float* U_w     = (const float*)d_in[5];
    const float* final_w = (const float*)d_in[6];
    const float* final_b = (const float*)d_in[7];
    float* out = (float*)d_out;

    const long long yhat_n  = (long long)B_ * Y_;                 // 71368
    const long long total_n = yhat_n + 1 + (long long)B_ * Y_ * L_;
    int write_loss  = (out_size >= (int)(yhat_n + 1)) ? 1 : 0;
    int write_alpha = ((long long)out_size >= total_n) ? 1 : 0;

    const int smem_bytes = (NKB * 4 * 32) * 16           // wS
                         + (NKB * 4 * 32) * 8            // wQ (hi only)
                         + 2 * (LCH * FPAIR) * 4         // hi/lo planes
                         + (LCH * 2) * 4                 // h2
                         + 32 * 16                       // w2
                         + (8 * 32 * 2 + YT + YT) * 4;   // zs, rs, iZ, lt
    cudaFuncSetAttribute(attn_kernel, cudaFuncAttributeMaxDynamicSharedMemorySize,
                         smem_bytes);

    conv_kernel<<<dim3(L_ / 64, B_), 256>>>(tokens, embed_W, conv_w, conv_b);

    float* out_alpha = out + yhat_n + 1;
    attn_kernel<<<dim3(NYT, B_), 256, smem_bytes>>>(
        U_w, final_w, final_b, target, out, out_alpha, write_alpha);

    if (write_loss)
        loss_kernel<<<1, 256>>>(out + yhat_n, B_ * NYT);
}

// round 15
// speedup vs baseline: 1.2214x; 1.2214x over previous
#include <cuda_runtime.h>
#include <cuda_bf16.h>
#include <math.h>
#include <stdint.h>

#define B_  8
#define L_  2048
#define E_  100
#define FM_ 50
#define Y_  8921
#define K_  9

#define YT    32          // labels per attn block
#define NYT   279         // ceil(Y_/YT)
#define FPAIR 28          // bf16-pair row stride (24 real pairs + 4 pad)
#define LCH   256         // positions per chunk
#define NCHK  (L_ / LCH)  // 8
#define NKB   3           // k-steps of 16 covering f 0..47; f 48,49 via fp32 fixup
#define LOG2E 1.4426950408889634f

// scratch (static device arrays are allowed)
__device__ uint32_t g_hhi[(size_t)B_ * L_ * FPAIR];   // bf16 hi pairs [b][l][28]
__device__ uint32_t g_hlo[(size_t)B_ * L_ * FPAIR];   // bf16 lo pairs
__device__ float    g_h2 [(size_t)B_ * L_ * 2];       // fp32 h for f=48,49
__device__ float    g_losspart[B_ * NYT];

// ---- bf16 helpers ----------------------------------------------------------
__device__ __forceinline__ uint32_t pack_bf2(__nv_bfloat16 a, __nv_bfloat16 b) {
    return (uint32_t)__bfloat16_as_ushort(a) |
           ((uint32_t)__bfloat16_as_ushort(b) << 16);
}
__device__ __forceinline__ void split_bf(float x, __nv_bfloat16& h, __nv_bfloat16& l) {
    h = __float2bfloat16(x);
    l = __float2bfloat16(x - __bfloat162float(h));
}
__device__ __forceinline__ void mma_bf16(float d[4], const uint32_t a[4],
                                         uint32_t b0, uint32_t b1) {
    asm("mma.sync.aligned.m16n8k16.row.col.f32.bf16.bf16.f32 "
        "{%0,%1,%2,%3},{%4,%5,%6,%7},{%8,%9},{%0,%1,%2,%3};"
        : "+f"(d[0]), "+f"(d[1]), "+f"(d[2]), "+f"(d[3])
        : "r"(a[0]), "r"(a[1]), "r"(a[2]), "r"(a[3]), "r"(b0), "r"(b1));
}

// ---------------------------------------------------------------------------
// Kernel 1: embed + conv1d(K=9) + bias + tanh.
// f 0..47 -> bf16 hi/lo pair planes; f 48,49 -> fp32 g_h2. (unchanged, proven)
// ---------------------------------------------------------------------------
__global__ void __launch_bounds__(256) conv_kernel(
    const int* __restrict__ tokens,
    const float* __restrict__ embed_W,
    const float* __restrict__ conv_w,
    const float* __restrict__ conv_b)
{
    __shared__ int   tok_s[72];
    __shared__ float x_s[72][21];
    __shared__ float w_s[50][20][9];

    const int tid   = threadIdx.x;
    const int b     = blockIdx.y;
    const int lbase = blockIdx.x * 64;

    if (tid < 72) {
        int gl = lbase + tid - 4;
        tok_s[tid] = (gl >= 0 && gl < L_) ? tokens[b * L_ + gl] : -1;
    }
    __syncthreads();

    const int f  = tid >> 2;
    const int lg = tid & 3;
    const int l0 = lg * 16;

    float acc[16];
#pragma unroll
    for (int j = 0; j < 16; j++) acc[j] = 0.f;

    for (int ec = 0; ec < 5; ec++) {
        for (int idx = tid; idx < 72 * 20; idx += 256) {
            int i = idx / 20, e = idx % 20;
            int t = tok_s[i];
            x_s[i][e] = (t >= 0) ? embed_W[(size_t)t * E_ + ec * 20 + e] : 0.f;
        }
        for (int idx = tid; idx < 50 * 20 * 9; idx += 256) {
            int ff = idx / 180, r = idx % 180;
            w_s[ff][r / 9][r % 9] = conv_w[ff * (E_ * K_) + ec * 180 + r];
        }
        __syncthreads();

        if (f < FM_) {
            for (int e = 0; e < 20; e++) {
                float xv[24];
#pragma unroll
                for (int t = 0; t < 24; t++) xv[t] = x_s[l0 + t][e];
                float wv[9];
#pragma unroll
                for (int k = 0; k < 9; k++) wv[k] = w_s[f][e][k];
#pragma unroll
                for (int k = 0; k < 9; k++)
#pragma unroll
                    for (int j = 0; j < 16; j++)
                        acc[j] += xv[j + k] * wv[k];
            }
        }
        __syncthreads();
    }

    if (f < FM_) {
        const float bias = conv_b[f];
        unsigned short* phi = (unsigned short*)g_hhi;
        unsigned short* plo = (unsigned short*)g_hlo;
#pragma unroll
        for (int j = 0; j < 16; j++) {
            int l = lbase + l0 + j;
            float v = tanhf(acc[j] + bias);
            if (f < 48) {
                __nv_bfloat16 hb, lb;
                split_bf(v, hb, lb);
                size_t o = ((size_t)b * L_ + l) * (2 * FPAIR) + f;
                phi[o] = __bfloat16_as_ushort(hb);
                plo[o] = __bfloat16_as_ushort(lb);
            } else {
                g_h2[((size_t)b * L_ + l) * 2 + (f - 48)] = v;
            }
        }
    }
}

// ---------------------------------------------------------------------------
// Kernel 2: label attention — proven R13 structure (single phase, write e,
// vectorized L2-hot rescale) with Q cut to 1-term bf16 (validated in R14:
// rel_err 7.7e-6). S stays 3-term + exact fp32 fixup for f=48,49.
// block = (32 labels, b), 256 threads = 8 warps, 2 CTAs/SM.
// ---------------------------------------------------------------------------
__global__ void __launch_bounds__(256, 2) attn_kernel(
    const float* __restrict__ U_w,
    const float* __restrict__ final_w,
    const float* __restrict__ final_b,
    const float* __restrict__ target,
    float* __restrict__ out_yhat,
    float* __restrict__ out_alpha,
    int write_alpha)
{
    extern __shared__ __align__(16) unsigned char smraw[];
    uint4*    wS   = (uint4*)smraw;                    // [NKB*4*32] 6144 B
    uint2*    wQ   = (uint2*)(wS + NKB * 4 * 32);      // hi-only    3072 B
    uint32_t* smhi = (uint32_t*)(wQ + NKB * 4 * 32);   // [LCH*FPAIR] 28672 B
    uint32_t* smlo = smhi + LCH * FPAIR;               // 28672 B
    float*    h2s  = (float*)(smlo + LCH * FPAIR);     // [LCH*2] 2048 B
    float4*   w2s  = (float4*)(h2s + LCH * 2);         // [32] 512 B
    float*    zs   = (float*)(w2s + 32);               // [8*32]
    float*    rs   = zs + 8 * 32;                      // [8*32]
    float*    iZ_s = rs + 8 * 32;                      // [32]
    float*    lt   = iZ_s + YT;                        // [32]

    const int tid  = threadIdx.x;
    const int lane = tid & 31;
    const int warp = tid >> 5;
    const int b    = blockIdx.y;
    const int y0t  = blockIdx.x * YT;

    const int g = lane >> 2;       // mma groupID (0..7)
    const int t = lane & 3;        // mma thread-in-group (0..3)

    // ---- fragment-order weights: S hi/lo (U pre-scaled by log2e), Q hi only
    for (int idx = tid; idx < NKB * 4 * 32; idx += 256) {
        int k  = idx >> 7;
        int nt = (idx >> 5) & 3;
        int ln = idx & 31;
        int gg = ln >> 2, tt = ln & 3;
        int gy = y0t + nt * 8 + gg;
        int f00 = k * 16 + 2 * tt, f01 = f00 + 1;
        int f10 = f00 + 8,         f11 = f10 + 1;
        float u00=0.f,u01=0.f,u10=0.f,u11=0.f, v00=0.f,v01=0.f,v10=0.f,v11=0.f;
        if (gy < Y_) {
            const float* up = U_w     + gy * FM_;
            const float* vp = final_w + gy * FM_;
            u00 = up[f00] * LOG2E; v00 = vp[f00];
            u01 = up[f01] * LOG2E; v01 = vp[f01];
            u10 = up[f10] * LOG2E; v10 = vp[f10];
            u11 = up[f11] * LOG2E; v11 = vp[f11];
        }
        __nv_bfloat16 h00,l00,h01,l01,h10,l10,h11,l11;
        split_bf(u00,h00,l00); split_bf(u01,h01,l01);
        split_bf(u10,h10,l10); split_bf(u11,h11,l11);
        wS[idx] = make_uint4(pack_bf2(h00,h01), pack_bf2(h10,h11),
                             pack_bf2(l00,l01), pack_bf2(l10,l11));
        wQ[idx] = make_uint2(pack_bf2(__float2bfloat16(v00), __float2bfloat16(v01)),
                             pack_bf2(__float2bfloat16(v10), __float2bfloat16(v11)));
    }
    // fp32 fixup weights for f=48,49 (u's pre-scaled by log2e)
    if (tid < YT) {
        int gy = y0t + tid;
        float4 w = make_float4(0.f, 0.f, 0.f, 0.f);
        if (gy < Y_) {
            w.x = U_w[gy * FM_ + 48] * LOG2E;
            w.y = U_w[gy * FM_ + 49] * LOG2E;
            w.z = final_w[gy * FM_ + 48];
            w.w = final_w[gy * FM_ + 49];
        }
        w2s[tid] = w;
    }

    // lane-local Z,R: label = nt*8 + 2t + p
    float Zl[4][2] = {{0.f,0.f},{0.f,0.f},{0.f,0.f},{0.f,0.f}};
    float Rl[4][2] = {{0.f,0.f},{0.f,0.f},{0.f,0.f},{0.f,0.f}};

    const size_t arow0 = (size_t)b * Y_;
    const int prow0 = warp * 32;   // warp's first position row within chunk

    for (int ch = 0; ch < NCHK; ch++) {
        __syncthreads();   // previous chunk readers done (covers weight build)
        {   // stage both planes + h2: contiguous uint4/float4
            const uint4* shi = (const uint4*)(g_hhi +
                ((size_t)b * L_ + (size_t)ch * LCH) * FPAIR);
            const uint4* slo = (const uint4*)(g_hlo +
                ((size_t)b * L_ + (size_t)ch * LCH) * FPAIR);
            uint4* dhi = (uint4*)smhi;
            uint4* dlo = (uint4*)smlo;
#pragma unroll
            for (int i = tid; i < LCH * FPAIR / 4; i += 256) {
                dhi[i] = shi[i];
                dlo[i] = slo[i];
            }
            const float4* sh2 = (const float4*)(g_h2 +
                ((size_t)b * L_ + (size_t)ch * LCH) * 2);
            if (tid < LCH * 2 / 4) ((float4*)h2s)[tid] = sh2[tid];
        }
        __syncthreads();

        float accS[2][4][4] = {};
        float accQ[2][4][4] = {};

#pragma unroll
        for (int k = 0; k < NKB; k++) {
            uint32_t ahi[2][4], alo[2][4];
#pragma unroll
            for (int mt = 0; mt < 2; mt++) {
                const int r0 = prow0 + mt * 16;
                const int pa = k * 8 + t;
                ahi[mt][0] = smhi[(r0 + g)     * FPAIR + pa];
                ahi[mt][1] = smhi[(r0 + g + 8) * FPAIR + pa];
                ahi[mt][2] = smhi[(r0 + g)     * FPAIR + pa + 4];
                ahi[mt][3] = smhi[(r0 + g + 8) * FPAIR + pa + 4];
                alo[mt][0] = smlo[(r0 + g)     * FPAIR + pa];
                alo[mt][1] = smlo[(r0 + g + 8) * FPAIR + pa];
                alo[mt][2] = smlo[(r0 + g)     * FPAIR + pa + 4];
                alo[mt][3] = smlo[(r0 + g + 8) * FPAIR + pa + 4];
            }
#pragma unroll
            for (int nt = 0; nt < 4; nt++) {
                uint4 Bs = wS[(k * 4 + nt) * 32 + lane];
                uint2 Bq = wQ[(k * 4 + nt) * 32 + lane];
#pragma unroll
                for (int mt = 0; mt < 2; mt++) {
                    mma_bf16(accS[mt][nt], ahi[mt], Bs.x, Bs.y);  // ah*bh
                    mma_bf16(accS[mt][nt], ahi[mt], Bs.z, Bs.w);  // ah*bl
                    mma_bf16(accS[mt][nt], alo[mt], Bs.x, Bs.y);  // al*bh
                    mma_bf16(accQ[mt][nt], ahi[mt], Bq.x, Bq.y);  // Q 1-term
                }
            }
        }

        // exact fp32 fixup for features 48,49 (S and Q)
#pragma unroll
        for (int mt = 0; mt < 2; mt++) {
            const int pA = prow0 + mt * 16 + g;
            float hA0 = h2s[pA * 2],       hA1 = h2s[pA * 2 + 1];
            float hB0 = h2s[(pA + 8) * 2], hB1 = h2s[(pA + 8) * 2 + 1];
#pragma unroll
            for (int nt = 0; nt < 4; nt++) {
                float4 wa = w2s[nt * 8 + 2 * t];
                float4 wb = w2s[nt * 8 + 2 * t + 1];
                accS[mt][nt][0] += hA0 * wa.x + hA1 * wa.y;
                accS[mt][nt][1] += hA0 * wb.x + hA1 * wb.y;
                accS[mt][nt][2] += hB0 * wa.x + hB1 * wa.y;
                accS[mt][nt][3] += hB0 * wb.x + hB1 * wb.y;
                accQ[mt][nt][0] += hA0 * wa.z + hA1 * wa.w;
                accQ[mt][nt][1] += hA0 * wb.z + hA1 * wb.w;
                accQ[mt][nt][2] += hB0 * wa.z + hB1 * wa.w;
                accQ[mt][nt][3] += hB0 * wb.z + hB1 * wb.w;
            }
        }

        // per-chunk epilogue (e = exp2(s*log2e) = exp(s)), write e to gmem
        const int chb = ch * LCH;
#pragma unroll
        for (int mt = 0; mt < 2; mt++) {
            const int posA = chb + prow0 + mt * 16 + g;
            const int posB = posA + 8;
#pragma unroll
            for (int nt = 0; nt < 4; nt++) {
                const int lab0 = y0t + nt * 8 + 2 * t;
                const int lab1 = lab0 + 1;
                float e0 = exp2f(accS[mt][nt][0]);
                float e1 = exp2f(accS[mt][nt][1]);
                float e2 = exp2f(accS[mt][nt][2]);
                float e3 = exp2f(accS[mt][nt][3]);
                Zl[nt][0] += e0 + e2;
                Zl[nt][1] += e1 + e3;
                Rl[nt][0] += e0 * accQ[mt][nt][0] + e2 * accQ[mt][nt][2];
                Rl[nt][1] += e1 * accQ[mt][nt][1] + e3 * accQ[mt][nt][3];
                if (write_alpha) {
                    if (lab0 < Y_) {
                        float* rp = out_alpha + (arow0 + lab0) * L_;
                        rp[posA] = e0; rp[posB] = e2;
                    }
                    if (lab1 < Y_) {
                        float* rp = out_alpha + (arow0 + lab1) * L_;
                        rp[posA] = e1; rp[posB] = e3;
                    }
                }
            }
        }
    }

    // reduce over g (lane bits 2,3,4)
#pragma unroll
    for (int o = 4; o <= 16; o <<= 1) {
#pragma unroll
        for (int nt = 0; nt < 4; nt++) {
            Zl[nt][0] += __shfl_xor_sync(0xffffffffu, Zl[nt][0], o);
            Zl[nt][1] += __shfl_xor_sync(0xffffffffu, Zl[nt][1], o);
            Rl[nt][0] += __shfl_xor_sync(0xffffffffu, Rl[nt][0], o);
            Rl[nt][1] += __shfl_xor_sync(0xffffffffu, Rl[nt][1], o);
        }
    }
    if (lane < 4) {
#pragma unroll
        for (int nt = 0; nt < 4; nt++) {
            zs[warp * 32 + nt * 8 + 2 * lane + 0] = Zl[nt][0];
            zs[warp * 32 + nt * 8 + 2 * lane + 1] = Zl[nt][1];
            rs[warp * 32 + nt * 8 + 2 * lane + 0] = Rl[nt][0];
            rs[warp * 32 + nt * 8 + 2 * lane + 1] = Rl[nt][1];
        }
    }
    __syncthreads();

    // cross-warp combine + yhat + loss terms
    if (tid < YT) {
        float Z = 0.f, R = 0.f;
#pragma unroll
        for (int w = 0; w < 8; w++) { Z += zs[w * 32 + tid]; R += rs[w * 32 + tid]; }
        iZ_s[tid] = 1.f / Z;
        float lossterm = 0.f;
        int gy = y0t + tid;
        if (gy < Y_) {
            float r  = R / Z + final_b[gy];
            float yh = 1.f / (1.f + expf(-r));
            out_yhat[b * Y_ + gy] = yh;
            float tg = target[b * Y_ + gy];
            lossterm = tg * logf(yh + 1e-12f) + (1.f - tg) * logf(1.f - yh + 1e-12f);
        }
        lt[tid] = lossterm;
    }
    __syncthreads();
    if (tid == 0) {
        float s = 0.f;
#pragma unroll
        for (int i = 0; i < YT; i++) s += lt[i];
        g_losspart[b * gridDim.x + blockIdx.x] = s;
    }

    // in-place rescale (L2-hot). Alpha region sits at odd float offset:
    // element c==3 (mod 4) of each row is 16B-aligned -> scalar head (0,1,2) +
    // 511 float4 + scalar tail (2047).
    if (write_alpha) {
#pragma unroll
        for (int i = 0; i < 4; i++) {
            int yl = warp * 4 + i;
            int gy = y0t + yl;
            if (gy >= Y_) continue;
            float iZ = iZ_s[yl];
            float* ap = out_alpha + (arow0 + gy) * L_;
            if (lane == 0) { ap[0] *= iZ; ap[1] *= iZ; ap[2] *= iZ; ap[2047] *= iZ; }
            float4* v = (float4*)(ap + 3);
#pragma unroll 4
            for (int j = lane; j < 511; j += 32) {
                float4 x = v[j];
                x.x *= iZ; x.y *= iZ; x.z *= iZ; x.w *= iZ;
                v[j] = x;
            }
        }
    }
}

// ---------------------------------------------------------------------------
// Kernel 3: deterministic loss reduction
// ---------------------------------------------------------------------------
__global__ void loss_kernel(float* __restrict__ out_loss, int npart)
{
    __shared__ float red[256];
    float s = 0.f;
    for (int i = threadIdx.x; i < npart; i += 256) s += g_losspart[i];
    red[threadIdx.x] = s;
    __syncthreads();
    for (int o = 128; o > 0; o >>= 1) {
        if (threadIdx.x < o) red[threadIdx.x] += red[threadIdx.x + o];
        __syncthreads();
    }
    if (threadIdx.x == 0) *out_loss = -red[0] / (float)(B_ * Y_);
}

// ---------------------------------------------------------------------------
extern "C" void kernel_launch(void* const* d_in, const int* in_sizes, int n_in,
                              void* d_out, int out_size)
{
    const int*   tokens  = (const int*)  d_in[0];
    const float* target  = (const float*)d_in[1];
    const float* embed_W = (const float*)d_in[2];
    const float* conv_w  = (const float*)d_in[3];
    const float* conv_b  = (const float*)d_in[4];
    const float* U_w     = (const float*)d_in[5];
    const float* final_w = (const float*)d_in[6];
    const float* final_b = (const float*)d_in[7];
    float* out = (float*)d_out;

    const long long yhat_n  = (long long)B_ * Y_;                 // 71368
    const long long total_n = yhat_n + 1 + (long long)B_ * Y_ * L_;
    int write_loss  = (out_size >= (int)(yhat_n + 1)) ? 1 : 0;
    int write_alpha = ((long long)out_size >= total_n) ? 1 : 0;

    const int smem_bytes = (NKB * 4 * 32) * 16           // wS
                         + (NKB * 4 * 32) * 8            // wQ (hi only)
                         + 2 * (LCH * FPAIR) * 4         // hi/lo planes
                         + (LCH * 2) * 4                 // h2
                         + 32 * 16                       // w2
                         + (8 * 32 * 2 + YT + YT) * 4;   // zs, rs, iZ, lt
    cudaFuncSetAttribute(attn_kernel, cudaFuncAttributeMaxDynamicSharedMemorySize,
                         smem_bytes);

    conv_kernel<<<dim3(L_ / 64, B_), 256>>>(tokens, embed_W, conv_w, conv_b);

    float* out_alpha = out + yhat_n + 1;
    attn_kernel<<<dim3(NYT, B_), 256, smem_bytes>>>(
        U_w, final_w, final_b, target, out, out_alpha, write_alpha);

    if (write_loss)
        loss_kernel<<<1, 256>>>(out + yhat_n, B_ * NYT);
}

// round 16
// speedup vs baseline: 1.3052x; 1.0686x over previous
#include <cuda_runtime.h>
#include <cuda_bf16.h>
#include <math.h>
#include <stdint.h>

#define B_  8
#define L_  2048
#define E_  100
#define FM_ 50
#define Y_  8921
#define K_  9

#define YT    32          // labels per attn block
#define NYT   279         // ceil(Y_/YT)
#define FPAIR 28          // bf16-pair row stride (24 real pairs + 4 pad)
#define LCH   128         // positions per chunk (1 M-tile of 16 per warp)
#define NCHK  (L_ / LCH)  // 16
#define NKB   3           // k-steps of 16 covering f 0..47; f 48,49 via fp32 fixup
#define LOG2E 1.4426950408889634f

// scratch (static device arrays are allowed)
__device__ uint32_t g_hhi[(size_t)B_ * L_ * FPAIR];   // bf16 hi pairs [b][l][28]
__device__ uint32_t g_hlo[(size_t)B_ * L_ * FPAIR];   // bf16 lo pairs
__device__ float    g_h2 [(size_t)B_ * L_ * 2];       // fp32 h for f=48,49
__device__ float    g_losspart[B_ * NYT];

// ---- bf16 helpers ----------------------------------------------------------
__device__ __forceinline__ uint32_t pack_bf2(__nv_bfloat16 a, __nv_bfloat16 b) {
    return (uint32_t)__bfloat16_as_ushort(a) |
           ((uint32_t)__bfloat16_as_ushort(b) << 16);
}
__device__ __forceinline__ void split_bf(float x, __nv_bfloat16& h, __nv_bfloat16& l) {
    h = __float2bfloat16(x);
    l = __float2bfloat16(x - __bfloat162float(h));
}
__device__ __forceinline__ void mma_bf16(float d[4], const uint32_t a[4],
                                         uint32_t b0, uint32_t b1) {
    asm("mma.sync.aligned.m16n8k16.row.col.f32.bf16.bf16.f32 "
        "{%0,%1,%2,%3},{%4,%5,%6,%7},{%8,%9},{%0,%1,%2,%3};"
        : "+f"(d[0]), "+f"(d[1]), "+f"(d[2]), "+f"(d[3])
        : "r"(a[0]), "r"(a[1]), "r"(a[2]), "r"(a[3]), "r"(b0), "r"(b1));
}

// ---------------------------------------------------------------------------
// Kernel 1: embed + conv1d(K=9) + bias + tanh.
// f 0..47 -> bf16 hi/lo pair planes; f 48,49 -> fp32 g_h2. (unchanged, proven)
// ---------------------------------------------------------------------------
__global__ void __launch_bounds__(256) conv_kernel(
    const int* __restrict__ tokens,
    const float* __restrict__ embed_W,
    const float* __restrict__ conv_w,
    const float* __restrict__ conv_b)
{
    __shared__ int   tok_s[72];
    __shared__ float x_s[72][21];
    __shared__ float w_s[50][20][9];

    const int tid   = threadIdx.x;
    const int b     = blockIdx.y;
    const int lbase = blockIdx.x * 64;

    if (tid < 72) {
        int gl = lbase + tid - 4;
        tok_s[tid] = (gl >= 0 && gl < L_) ? tokens[b * L_ + gl] : -1;
    }
    __syncthreads();

    const int f  = tid >> 2;
    const int lg = tid & 3;
    const int l0 = lg * 16;

    float acc[16];
#pragma unroll
    for (int j = 0; j < 16; j++) acc[j] = 0.f;

    for (int ec = 0; ec < 5; ec++) {
        for (int idx = tid; idx < 72 * 20; idx += 256) {
            int i = idx / 20, e = idx % 20;
            int t = tok_s[i];
            x_s[i][e] = (t >= 0) ? embed_W[(size_t)t * E_ + ec * 20 + e] : 0.f;
        }
        for (int idx = tid; idx < 50 * 20 * 9; idx += 256) {
            int ff = idx / 180, r = idx % 180;
            w_s[ff][r / 9][r % 9] = conv_w[ff * (E_ * K_) + ec * 180 + r];
        }
        __syncthreads();

        if (f < FM_) {
            for (int e = 0; e < 20; e++) {
                float xv[24];
#pragma unroll
                for (int t = 0; t < 24; t++) xv[t] = x_s[l0 + t][e];
                float wv[9];
#pragma unroll
                for (int k = 0; k < 9; k++) wv[k] = w_s[f][e][k];
#pragma unroll
                for (int k = 0; k < 9; k++)
#pragma unroll
                    for (int j = 0; j < 16; j++)
                        acc[j] += xv[j + k] * wv[k];
            }
        }
        __syncthreads();
    }

    if (f < FM_) {
        const float bias = conv_b[f];
        unsigned short* phi = (unsigned short*)g_hhi;
        unsigned short* plo = (unsigned short*)g_hlo;
#pragma unroll
        for (int j = 0; j < 16; j++) {
            int l = lbase + l0 + j;
            float v = tanhf(acc[j] + bias);
            if (f < 48) {
                __nv_bfloat16 hb, lb;
                split_bf(v, hb, lb);
                size_t o = ((size_t)b * L_ + l) * (2 * FPAIR) + f;
                phi[o] = __bfloat16_as_ushort(hb);
                plo[o] = __bfloat16_as_ushort(lb);
            } else {
                g_h2[((size_t)b * L_ + l) * 2 + (f - 48)] = v;
            }
        }
    }
}

// ---------------------------------------------------------------------------
// Kernel 2: label attention — R15 math (S 3-term + Q 1-term bf16 mma,
// fp32 fixup f=48,49, single phase, write e, L2-hot vector rescale) with
// LCH=128 so each warp holds ONE 16-row M-tile -> ~84 regs -> 3 CTAs/SM.
// block = (32 labels, b), 256 threads = 8 warps.
// ---------------------------------------------------------------------------
__global__ void __launch_bounds__(256, 3) attn_kernel(
    const float* __restrict__ U_w,
    const float* __restrict__ final_w,
    const float* __restrict__ final_b,
    const float* __restrict__ target,
    float* __restrict__ out_yhat,
    float* __restrict__ out_alpha,
    int write_alpha)
{
    extern __shared__ __align__(16) unsigned char smraw[];
    uint4*    wS   = (uint4*)smraw;                    // [NKB*4*32] 6144 B
    uint2*    wQ   = (uint2*)(wS + NKB * 4 * 32);      // hi-only    3072 B
    uint32_t* smhi = (uint32_t*)(wQ + NKB * 4 * 32);   // [LCH*FPAIR] 14336 B
    uint32_t* smlo = smhi + LCH * FPAIR;               // 14336 B
    float*    h2s  = (float*)(smlo + LCH * FPAIR);     // [LCH*2] 1024 B
    float4*   w2s  = (float4*)(h2s + LCH * 2);         // [32] 512 B
    float*    zs   = (float*)(w2s + 32);               // [8*32]
    float*    rs   = zs + 8 * 32;                      // [8*32]
    float*    iZ_s = rs + 8 * 32;                      // [32]
    float*    lt   = iZ_s + YT;                        // [32]

    const int tid  = threadIdx.x;
    const int lane = tid & 31;
    const int warp = tid >> 5;
    const int b    = blockIdx.y;
    const int y0t  = blockIdx.x * YT;

    const int g = lane >> 2;       // mma groupID (0..7)
    const int t = lane & 3;        // mma thread-in-group (0..3)

    // ---- fragment-order weights: S hi/lo (U pre-scaled by log2e), Q hi only
    for (int idx = tid; idx < NKB * 4 * 32; idx += 256) {
        int k  = idx >> 7;
        int nt = (idx >> 5) & 3;
        int ln = idx & 31;
        int gg = ln >> 2, tt = ln & 3;
        int gy = y0t + nt * 8 + gg;
        int f00 = k * 16 + 2 * tt, f01 = f00 + 1;
        int f10 = f00 + 8,         f11 = f10 + 1;
        float u00=0.f,u01=0.f,u10=0.f,u11=0.f, v00=0.f,v01=0.f,v10=0.f,v11=0.f;
        if (gy < Y_) {
            const float* up = U_w     + gy * FM_;
            const float* vp = final_w + gy * FM_;
            u00 = up[f00] * LOG2E; v00 = vp[f00];
            u01 = up[f01] * LOG2E; v01 = vp[f01];
            u10 = up[f10] * LOG2E; v10 = vp[f10];
            u11 = up[f11] * LOG2E; v11 = vp[f11];
        }
        __nv_bfloat16 h00,l00,h01,l01,h10,l10,h11,l11;
        split_bf(u00,h00,l00); split_bf(u01,h01,l01);
        split_bf(u10,h10,l10); split_bf(u11,h11,l11);
        wS[idx] = make_uint4(pack_bf2(h00,h01), pack_bf2(h10,h11),
                             pack_bf2(l00,l01), pack_bf2(l10,l11));
        wQ[idx] = make_uint2(pack_bf2(__float2bfloat16(v00), __float2bfloat16(v01)),
                             pack_bf2(__float2bfloat16(v10), __float2bfloat16(v11)));
    }
    // fp32 fixup weights for f=48,49 (u's pre-scaled by log2e)
    if (tid < YT) {
        int gy = y0t + tid;
        float4 w = make_float4(0.f, 0.f, 0.f, 0.f);
        if (gy < Y_) {
            w.x = U_w[gy * FM_ + 48] * LOG2E;
            w.y = U_w[gy * FM_ + 49] * LOG2E;
            w.z = final_w[gy * FM_ + 48];
            w.w = final_w[gy * FM_ + 49];
        }
        w2s[tid] = w;
    }

    // lane-local Z,R: label = nt*8 + 2t + p
    float Zl[4][2] = {{0.f,0.f},{0.f,0.f},{0.f,0.f},{0.f,0.f}};
    float Rl[4][2] = {{0.f,0.f},{0.f,0.f},{0.f,0.f},{0.f,0.f}};

    const size_t arow0 = (size_t)b * Y_;
    const int prow0 = warp * 16;   // warp's M-tile row base within chunk

    for (int ch = 0; ch < NCHK; ch++) {
        __syncthreads();   // previous chunk readers done (covers weight build)
        {   // stage both planes + h2: contiguous uint4/float4
            const uint4* shi = (const uint4*)(g_hhi +
                ((size_t)b * L_ + (size_t)ch * LCH) * FPAIR);
            const uint4* slo = (const uint4*)(g_hlo +
                ((size_t)b * L_ + (size_t)ch * LCH) * FPAIR);
            uint4* dhi = (uint4*)smhi;
            uint4* dlo = (uint4*)smlo;
#pragma unroll
            for (int i = tid; i < LCH * FPAIR / 4; i += 256) {
                dhi[i] = shi[i];
                dlo[i] = slo[i];
            }
            const float4* sh2 = (const float4*)(g_h2 +
                ((size_t)b * L_ + (size_t)ch * LCH) * 2);
            if (tid < LCH * 2 / 4) ((float4*)h2s)[tid] = sh2[tid];
        }
        __syncthreads();

        float accS[4][4] = {};
        float accQ[4][4] = {};

#pragma unroll
        for (int k = 0; k < NKB; k++) {
            uint32_t ahi[4], alo[4];
            {
                const int r0 = prow0;
                const int pa = k * 8 + t;
                ahi[0] = smhi[(r0 + g)     * FPAIR + pa];
                ahi[1] = smhi[(r0 + g + 8) * FPAIR + pa];
                ahi[2] = smhi[(r0 + g)     * FPAIR + pa + 4];
                ahi[3] = smhi[(r0 + g + 8) * FPAIR + pa + 4];
                alo[0] = smlo[(r0 + g)     * FPAIR + pa];
                alo[1] = smlo[(r0 + g + 8) * FPAIR + pa];
                alo[2] = smlo[(r0 + g)     * FPAIR + pa + 4];
                alo[3] = smlo[(r0 + g + 8) * FPAIR + pa + 4];
            }
#pragma unroll
            for (int nt = 0; nt < 4; nt++) {
                uint4 Bs = wS[(k * 4 + nt) * 32 + lane];
                uint2 Bq = wQ[(k * 4 + nt) * 32 + lane];
                mma_bf16(accS[nt], ahi, Bs.x, Bs.y);  // ah*bh
                mma_bf16(accS[nt], ahi, Bs.z, Bs.w);  // ah*bl
                mma_bf16(accS[nt], alo, Bs.x, Bs.y);  // al*bh
                mma_bf16(accQ[nt], ahi, Bq.x, Bq.y);  // Q 1-term
            }
        }

        // exact fp32 fixup for features 48,49 (S and Q)
        {
            const int pA = prow0 + g;
            float hA0 = h2s[pA * 2],       hA1 = h2s[pA * 2 + 1];
            float hB0 = h2s[(pA + 8) * 2], hB1 = h2s[(pA + 8) * 2 + 1];
#pragma unroll
            for (int nt = 0; nt < 4; nt++) {
                float4 wa = w2s[nt * 8 + 2 * t];
                float4 wb = w2s[nt * 8 + 2 * t + 1];
                accS[nt][0] += hA0 * wa.x + hA1 * wa.y;
                accS[nt][1] += hA0 * wb.x + hA1 * wb.y;
                accS[nt][2] += hB0 * wa.x + hB1 * wa.y;
                accS[nt][3] += hB0 * wb.x + hB1 * wb.y;
                accQ[nt][0] += hA0 * wa.z + hA1 * wa.w;
                accQ[nt][1] += hA0 * wb.z + hA1 * wb.w;
                accQ[nt][2] += hB0 * wa.z + hB1 * wa.w;
                accQ[nt][3] += hB0 * wb.z + hB1 * wb.w;
            }
        }

        // per-chunk epilogue (e = exp2(s*log2e) = exp(s)), write e to gmem
        {
            const int posA = ch * LCH + prow0 + g;
            const int posB = posA + 8;
#pragma unroll
            for (int nt = 0; nt < 4; nt++) {
                const int lab0 = y0t + nt * 8 + 2 * t;
                const int lab1 = lab0 + 1;
                float e0 = exp2f(accS[nt][0]);
                float e1 = exp2f(accS[nt][1]);
                float e2 = exp2f(accS[nt][2]);
                float e3 = exp2f(accS[nt][3]);
                Zl[nt][0] += e0 + e2;
                Zl[nt][1] += e1 + e3;
                Rl[nt][0] += e0 * accQ[nt][0] + e2 * accQ[nt][2];
                Rl[nt][1] += e1 * accQ[nt][1] + e3 * accQ[nt][3];
                if (write_alpha) {
                    if (lab0 < Y_) {
                        float* rp = out_alpha + (arow0 + lab0) * L_;
                        rp[posA] = e0; rp[posB] = e2;
                    }
                    if (lab1 < Y_) {
                        float* rp = out_alpha + (arow0 + lab1) * L_;
                        rp[posA] = e1; rp[posB] = e3;
                    }
                }
            }
        }
    }

    // reduce over g (lane bits 2,3,4)
#pragma unroll
    for (int o = 4; o <= 16; o <<= 1) {
#pragma unroll
        for (int nt = 0; nt < 4; nt++) {
            Zl[nt][0] += __shfl_xor_sync(0xffffffffu, Zl[nt][0], o);
            Zl[nt][1] += __shfl_xor_sync(0xffffffffu, Zl[nt][1], o);
            Rl[nt][0] += __shfl_xor_sync(0xffffffffu, Rl[nt][0], o);
            Rl[nt][1] += __shfl_xor_sync(0xffffffffu, Rl[nt][1], o);
        }
    }
    if (lane < 4) {
#pragma unroll
        for (int nt = 0; nt < 4; nt++) {
            zs[warp * 32 + nt * 8 + 2 * lane + 0] = Zl[nt][0];
            zs[warp * 32 + nt * 8 + 2 * lane + 1] = Zl[nt][1];
            rs[warp * 32 + nt * 8 + 2 * lane + 0] = Rl[nt][0];
            rs[warp * 32 + nt * 8 + 2 * lane + 1] = Rl[nt][1];
        }
    }
    __syncthreads();

    // cross-warp combine + yhat + loss terms
    if (tid < YT) {
        float Z = 0.f, R = 0.f;
#pragma unroll
        for (int w = 0; w < 8; w++) { Z += zs[w * 32 + tid]; R += rs[w * 32 + tid]; }
        iZ_s[tid] = 1.f / Z;
        float lossterm = 0.f;
        int gy = y0t + tid;
        if (gy < Y_) {
            float r  = R / Z + final_b[gy];
            float yh = 1.f / (1.f + expf(-r));
            out_yhat[b * Y_ + gy] = yh;
            float tg = target[b * Y_ + gy];
            lossterm = tg * logf(yh + 1e-12f) + (1.f - tg) * logf(1.f - yh + 1e-12f);
        }
        lt[tid] = lossterm;
    }
    __syncthreads();
    if (tid == 0) {
        float s = 0.f;
#pragma unroll
        for (int i = 0; i < YT; i++) s += lt[i];
        g_losspart[b * gridDim.x + blockIdx.x] = s;
    }

    // in-place rescale (L2-hot). Alpha region sits at odd float offset:
    // element c==3 (mod 4) of each row is 16B-aligned -> scalar head (0,1,2) +
    // 511 float4 + scalar tail (2047).
    if (write_alpha) {
#pragma unroll
        for (int i = 0; i < 4; i++) {
            int yl = warp * 4 + i;
            int gy = y0t + yl;
            if (gy >= Y_) continue;
            float iZ = iZ_s[yl];
            float* ap = out_alpha + (arow0 + gy) * L_;
            if (lane == 0) { ap[0] *= iZ; ap[1] *= iZ; ap[2] *= iZ; ap[2047] *= iZ; }
            float4* v = (float4*)(ap + 3);
#pragma unroll 4
            for (int j = lane; j < 511; j += 32) {
                float4 x = v[j];
                x.x *= iZ; x.y *= iZ; x.z *= iZ; x.w *= iZ;
                v[j] = x;
            }
        }
    }
}

// ---------------------------------------------------------------------------
// Kernel 3: deterministic loss reduction
// ---------------------------------------------------------------------------
__global__ void loss_kernel(float* __restrict__ out_loss, int npart)
{
    __shared__ float red[256];
    float s = 0.f;
    for (int i = threadIdx.x; i < npart; i += 256) s += g_losspart[i];
    red[threadIdx.x] = s;
    __syncthreads();
    for (int o = 128; o > 0; o >>= 1) {
        if (threadIdx.x < o) red[threadIdx.x] += red[threadIdx.x + o];
        __syncthreads();
    }
    if (threadIdx.x == 0) *out_loss = -red[0] / (float)(B_ * Y_);
}

// ---------------------------------------------------------------------------
extern "C" void kernel_launch(void* const* d_in, const int* in_sizes, int n_in,
                              void* d_out, int out_size)
{
    const int*   tokens  = (const int*)  d_in[0];
    const float* target  = (const float*)d_in[1];
    const float* embed_W = (const float*)d_in[2];
    const float* conv_w  = (const float*)d_in[3];
    const float* conv_b  = (const float*)d_in[4];
    const float* U_w     = (const float*)d_in[5];
    const float* final_w = (const float*)d_in[6];
    const float* final_b = (const float*)d_in[7];
    float* out = (float*)d_out;

    const long long yhat_n  = (long long)B_ * Y_;                 // 71368
    const long long total_n = yhat_n + 1 + (long long)B_ * Y_ * L_;
    int write_loss  = (out_size >= (int)(yhat_n + 1)) ? 1 : 0;
    int write_alpha = ((long long)out_size >= total_n) ? 1 : 0;

    const int smem_bytes = (NKB * 4 * 32) * 16           // wS
                         + (NKB * 4 * 32) * 8            // wQ (hi only)
                         + 2 * (LCH * FPAIR) * 4         // hi/lo planes
                         + (LCH * 2) * 4                 // h2
                         + 32 * 16                       // w2
                         + (8 * 32 * 2 + YT + YT) * 4;   // zs, rs, iZ, lt
    cudaFuncSetAttribute(attn_kernel, cudaFuncAttributeMaxDynamicSharedMemorySize,
                         smem_bytes);

    conv_kernel<<<dim3(L_ / 64, B_), 256>>>(tokens, embed_W, conv_w, conv_b);

    float* out_alpha = out + yhat_n + 1;
    attn_kernel<<<dim3(NYT, B_), 256, smem_bytes>>>(
        U_w, final_w, final_b, target, out, out_alpha, write_alpha);

    if (write_loss)
        loss_kernel<<<1, 256>>>(out + yhat_n, B_ * NYT);
}

// round 17
// speedup vs baseline: 1.3253x; 1.0154x over previous
#include <cuda_runtime.h>
#include <cuda_bf16.h>
#include <math.h>
#include <stdint.h>

#define B_  8
#define L_  2048
#define E_  100
#define FM_ 50
#define Y_  8921
#define K_  9

#define YT    32          // labels per attn block
#define NYT   279         // ceil(Y_/YT)
#define FPAIR 28          // bf16-pair row stride (24 real pairs + 4 pad)
#define LCH   128         // positions per chunk (1 M-tile of 16 per warp)
#define NCHK  (L_ / LCH)  // 16
#define NKB   3           // k-steps of 16 covering f 0..47; f 48,49 via fp32 fixup
#define LOG2E 1.4426950408889634f

// scratch (static device arrays are allowed)
__device__ uint32_t g_hhi[(size_t)B_ * L_ * FPAIR];   // bf16 hi pairs [b][l][28]
__device__ uint32_t g_hlo[(size_t)B_ * L_ * FPAIR];   // bf16 lo pairs
__device__ float    g_h2 [(size_t)B_ * L_ * 2];       // fp32 h for f=48,49
__device__ float    g_losspart[B_ * NYT];

// ---- bf16 helpers ----------------------------------------------------------
__device__ __forceinline__ uint32_t pack_bf2(__nv_bfloat16 a, __nv_bfloat16 b) {
    return (uint32_t)__bfloat16_as_ushort(a) |
           ((uint32_t)__bfloat16_as_ushort(b) << 16);
}
__device__ __forceinline__ void split_bf(float x, __nv_bfloat16& h, __nv_bfloat16& l) {
    h = __float2bfloat16(x);
    l = __float2bfloat16(x - __bfloat162float(h));
}
__device__ __forceinline__ void mma_bf16(float d[4], const uint32_t a[4],
                                         uint32_t b0, uint32_t b1) {
    asm("mma.sync.aligned.m16n8k16.row.col.f32.bf16.bf16.f32 "
        "{%0,%1,%2,%3},{%4,%5,%6,%7},{%8,%9},{%0,%1,%2,%3};"
        : "+f"(d[0]), "+f"(d[1]), "+f"(d[2]), "+f"(d[3])
        : "r"(a[0]), "r"(a[1]), "r"(a[2]), "r"(a[3]), "r"(b0), "r"(b1));
}
// ---- cp.async helpers --------------------------------------------------------
__device__ __forceinline__ void cp_async16(uint32_t dst, const void* src) {
    asm volatile("cp.async.cg.shared.global [%0], [%1], 16;" :: "r"(dst), "l"(src));
}
#define CP_COMMIT() asm volatile("cp.async.commit_group;" ::: "memory")
#define CP_WAIT1()  asm volatile("cp.async.wait_group 1;"  ::: "memory")

// ---------------------------------------------------------------------------
// Kernel 1: embed + conv1d(K=9) + bias + tanh. 512 blocks (32 l's each) for
// better SM balance. f 0..47 -> bf16 hi/lo pair planes; f 48,49 -> fp32 g_h2.
// ---------------------------------------------------------------------------
__global__ void __launch_bounds__(256) conv_kernel(
    const int* __restrict__ tokens,
    const float* __restrict__ embed_W,
    const float* __restrict__ conv_w,
    const float* __restrict__ conv_b)
{
    __shared__ int   tok_s[40];
    __shared__ float x_s[40][21];
    __shared__ float w_s[50][20][9];

    const int tid   = threadIdx.x;
    const int b     = blockIdx.y;
    const int lbase = blockIdx.x * 32;

    if (tid < 40) {
        int gl = lbase + tid - 4;
        tok_s[tid] = (gl >= 0 && gl < L_) ? tokens[b * L_ + gl] : -1;
    }
    __syncthreads();

    const int f  = tid >> 2;     // 0..63 (valid < 50)
    const int lg = tid & 3;
    const int l0 = lg * 8;

    float acc[8];
#pragma unroll
    for (int j = 0; j < 8; j++) acc[j] = 0.f;

    for (int ec = 0; ec < 5; ec++) {
        for (int idx = tid; idx < 40 * 20; idx += 256) {
            int i = idx / 20, e = idx % 20;
            int t = tok_s[i];
            x_s[i][e] = (t >= 0) ? embed_W[(size_t)t * E_ + ec * 20 + e] : 0.f;
        }
        for (int idx = tid; idx < 50 * 20 * 9; idx += 256) {
            int ff = idx / 180, r = idx % 180;
            w_s[ff][r / 9][r % 9] = conv_w[ff * (E_ * K_) + ec * 180 + r];
        }
        __syncthreads();

        if (f < FM_) {
            for (int e = 0; e < 20; e++) {
                float xv[16];
#pragma unroll
                for (int t = 0; t < 16; t++) xv[t] = x_s[l0 + t][e];
                float wv[9];
#pragma unroll
                for (int k = 0; k < 9; k++) wv[k] = w_s[f][e][k];
#pragma unroll
                for (int k = 0; k < 9; k++)
#pragma unroll
                    for (int j = 0; j < 8; j++)
                        acc[j] += xv[j + k] * wv[k];
            }
        }
        __syncthreads();
    }

    if (f < FM_) {
        const float bias = conv_b[f];
        unsigned short* phi = (unsigned short*)g_hhi;
        unsigned short* plo = (unsigned short*)g_hlo;
#pragma unroll
        for (int j = 0; j < 8; j++) {
            int l = lbase + l0 + j;
            float v = tanhf(acc[j] + bias);
            if (f < 48) {
                __nv_bfloat16 hb, lb;
                split_bf(v, hb, lb);
                size_t o = ((size_t)b * L_ + l) * (2 * FPAIR) + f;
                phi[o] = __bfloat16_as_ushort(hb);
                plo[o] = __bfloat16_as_ushort(lb);
            } else {
                g_h2[((size_t)b * L_ + l) * 2 + (f - 48)] = v;
            }
        }
    }
}

// ---------------------------------------------------------------------------
// Kernel 2: label attention — R16 math (S 3-term + Q 1-term bf16 mma,
// fp32 fixup f=48,49, single phase, write e, L2-hot vector rescale),
// LCH=128 / 1 M-tile per warp / 3 CTAs/SM, now with cp.async
// double-buffered h staging (chunk ch+1 in flight while ch computes).
// block = (32 labels, b), 256 threads = 8 warps. smem ~70KB -> 3 CTAs/SM.
// ---------------------------------------------------------------------------
__global__ void __launch_bounds__(256, 3) attn_kernel(
    const float* __restrict__ U_w,
    const float* __restrict__ final_w,
    const float* __restrict__ final_b,
    const float* __restrict__ target,
    float* __restrict__ out_yhat,
    float* __restrict__ out_alpha,
    int write_alpha)
{
    extern __shared__ __align__(16) unsigned char smraw[];
    uint4*    wS   = (uint4*)smraw;                    // [NKB*4*32] 6144 B
    uint2*    wQ   = (uint2*)(wS + NKB * 4 * 32);      // hi-only    3072 B
    uint32_t* smhi = (uint32_t*)(wQ + NKB * 4 * 32);   // [2][LCH*FPAIR] 28672 B
    uint32_t* smlo = smhi + 2 * LCH * FPAIR;           // 28672 B
    float*    h2s  = (float*)(smlo + 2 * LCH * FPAIR); // [2][LCH*2] 2048 B
    float4*   w2s  = (float4*)(h2s + 2 * LCH * 2);     // [32] 512 B
    float*    zs   = (float*)(w2s + 32);               // [8*32]
    float*    rs   = zs + 8 * 32;                      // [8*32]
    float*    iZ_s = rs + 8 * 32;                      // [32]
    float*    lt   = iZ_s + YT;                        // [32]

    const int tid  = threadIdx.x;
    const int lane = tid & 31;
    const int warp = tid >> 5;
    const int b    = blockIdx.y;
    const int y0t  = blockIdx.x * YT;

    const int g = lane >> 2;       // mma groupID (0..7)
    const int t = lane & 3;        // mma thread-in-group (0..3)

    const uint32_t hi_b = (uint32_t)__cvta_generic_to_shared(smhi);
    const uint32_t lo_b = (uint32_t)__cvta_generic_to_shared(smlo);
    const uint32_t h2_b = (uint32_t)__cvta_generic_to_shared(h2s);

    // stage chunk c into buffer (c&1) via cp.async
#define STAGE(c) do {                                                        \
        const int _bu = (c) & 1;                                             \
        const uint4* _shi = (const uint4*)(g_hhi +                           \
            ((size_t)b * L_ + (size_t)(c) * LCH) * FPAIR);                   \
        const uint4* _slo = (const uint4*)(g_hlo +                           \
            ((size_t)b * L_ + (size_t)(c) * LCH) * FPAIR);                   \
        const uint32_t _dhi = hi_b + _bu * (LCH * FPAIR * 4);                \
        const uint32_t _dlo = lo_b + _bu * (LCH * FPAIR * 4);                \
        for (int _i = tid; _i < LCH * FPAIR / 4; _i += 256) {                \
            cp_async16(_dhi + _i * 16, _shi + _i);                           \
            cp_async16(_dlo + _i * 16, _slo + _i);                           \
        }                                                                    \
        const uint4* _sh2 = (const uint4*)(g_h2 +                            \
            ((size_t)b * L_ + (size_t)(c) * LCH) * 2);                       \
        if (tid < LCH * 2 / 4)                                               \
            cp_async16(h2_b + _bu * (LCH * 2 * 4) + tid * 16, _sh2 + tid);   \
    } while (0)

    // prologue: chunk 0 in flight while weights are built
    STAGE(0);
    CP_COMMIT();

    // ---- fragment-order weights: S hi/lo (U pre-scaled by log2e), Q hi only
    for (int idx = tid; idx < NKB * 4 * 32; idx += 256) {
        int k  = idx >> 7;
        int nt = (idx >> 5) & 3;
        int ln = idx & 31;
        int gg = ln >> 2, tt = ln & 3;
        int gy = y0t + nt * 8 + gg;
        int f00 = k * 16 + 2 * tt, f01 = f00 + 1;
        int f10 = f00 + 8,         f11 = f10 + 1;
        float u00=0.f,u01=0.f,u10=0.f,u11=0.f, v00=0.f,v01=0.f,v10=0.f,v11=0.f;
        if (gy < Y_) {
            const float* up = U_w     + gy * FM_;
            const float* vp = final_w + gy * FM_;
            u00 = up[f00] * LOG2E; v00 = vp[f00];
            u01 = up[f01] * LOG2E; v01 = vp[f01];
            u10 = up[f10] * LOG2E; v10 = vp[f10];
            u11 = up[f11] * LOG2E; v11 = vp[f11];
        }
        __nv_bfloat16 h00,l00,h01,l01,h10,l10,h11,l11;
        split_bf(u00,h00,l00); split_bf(u01,h01,l01);
        split_bf(u10,h10,l10); split_bf(u11,h11,l11);
        wS[idx] = make_uint4(pack_bf2(h00,h01), pack_bf2(h10,h11),
                             pack_bf2(l00,l01), pack_bf2(l10,l11));
        wQ[idx] = make_uint2(pack_bf2(__float2bfloat16(v00), __float2bfloat16(v01)),
                             pack_bf2(__float2bfloat16(v10), __float2bfloat16(v11)));
    }
    // fp32 fixup weights for f=48,49 (u's pre-scaled by log2e)
    if (tid < YT) {
        int gy = y0t + tid;
        float4 w = make_float4(0.f, 0.f, 0.f, 0.f);
        if (gy < Y_) {
            w.x = U_w[gy * FM_ + 48] * LOG2E;
            w.y = U_w[gy * FM_ + 49] * LOG2E;
            w.z = final_w[gy * FM_ + 48];
            w.w = final_w[gy * FM_ + 49];
        }
        w2s[tid] = w;
    }

    // lane-local Z,R: label = nt*8 + 2t + p
    float Zl[4][2] = {{0.f,0.f},{0.f,0.f},{0.f,0.f},{0.f,0.f}};
    float Rl[4][2] = {{0.f,0.f},{0.f,0.f},{0.f,0.f},{0.f,0.f}};

    const size_t arow0 = (size_t)b * Y_;
    const int prow0 = warp * 16;   // warp's M-tile row base within chunk

    for (int ch = 0; ch < NCHK; ch++) {
        // prefetch chunk ch+1 into the other buffer. WAR-safe: that buffer's
        // readers (compute of ch-1) all passed the barrier ending iter ch-1.
        if (ch + 1 < NCHK) STAGE(ch + 1);
        CP_COMMIT();          // always commit (possibly empty group)
        CP_WAIT1();           // all but newest group done => chunk ch staged
        __syncthreads();      // cross-thread visibility (also weight build @ch0)

        const int bofs  = (ch & 1) * LCH * FPAIR;
        const int b2ofs = (ch & 1) * LCH * 2;

        float accS[4][4] = {};
        float accQ[4][4] = {};

#pragma unroll
        for (int k = 0; k < NKB; k++) {
            uint32_t ahi[4], alo[4];
            {
                const int r0 = prow0;
                const int pa = k * 8 + t;
                ahi[0] = smhi[bofs + (r0 + g)     * FPAIR + pa];
                ahi[1] = smhi[bofs + (r0 + g + 8) * FPAIR + pa];
                ahi[2] = smhi[bofs + (r0 + g)     * FPAIR + pa + 4];
                ahi[3] = smhi[bofs + (r0 + g + 8) * FPAIR + pa + 4];
                alo[0] = smlo[bofs + (r0 + g)     * FPAIR + pa];
                alo[1] = smlo[bofs + (r0 + g + 8) * FPAIR + pa];
                alo[2] = smlo[bofs + (r0 + g)     * FPAIR + pa + 4];
                alo[3] = smlo[bofs + (r0 + g + 8) * FPAIR + pa + 4];
            }
#pragma unroll
            for (int nt = 0; nt < 4; nt++) {
                uint4 Bs = wS[(k * 4 + nt) * 32 + lane];
                uint2 Bq = wQ[(k * 4 + nt) * 32 + lane];
                mma_bf16(accS[nt], ahi, Bs.x, Bs.y);  // ah*bh
                mma_bf16(accS[nt], ahi, Bs.z, Bs.w);  // ah*bl
                mma_bf16(accS[nt], alo, Bs.x, Bs.y);  // al*bh
                mma_bf16(accQ[nt], ahi, Bq.x, Bq.y);  // Q 1-term
            }
        }

        // exact fp32 fixup for features 48,49 (S and Q)
        {
            const int pA = prow0 + g;
            float hA0 = h2s[b2ofs + pA * 2],       hA1 = h2s[b2ofs + pA * 2 + 1];
            float hB0 = h2s[b2ofs + (pA + 8) * 2], hB1 = h2s[b2ofs + (pA + 8) * 2 + 1];
#pragma unroll
            for (int nt = 0; nt < 4; nt++) {
                float4 wa = w2s[nt * 8 + 2 * t];
                float4 wb = w2s[nt * 8 + 2 * t + 1];
                accS[nt][0] += hA0 * wa.x + hA1 * wa.y;
                accS[nt][1] += hA0 * wb.x + hA1 * wb.y;
                accS[nt][2] += hB0 * wa.x + hB1 * wa.y;
                accS[nt][3] += hB0 * wb.x + hB1 * wb.y;
                accQ[nt][0] += hA0 * wa.z + hA1 * wa.w;
                accQ[nt][1] += hA0 * wb.z + hA1 * wb.w;
                accQ[nt][2] += hB0 * wa.z + hB1 * wa.w;
                accQ[nt][3] += hB0 * wb.z + hB1 * wb.w;
            }
        }

        // per-chunk epilogue (e = exp2(s*log2e) = exp(s)), write e to gmem
        {
            const int posA = ch * LCH + prow0 + g;
            const int posB = posA + 8;
#pragma unroll
            for (int nt = 0; nt < 4; nt++) {
                const int lab0 = y0t + nt * 8 + 2 * t;
                const int lab1 = lab0 + 1;
                float e0 = exp2f(accS[nt][0]);
                float e1 = exp2f(accS[nt][1]);
                float e2 = exp2f(accS[nt][2]);
                float e3 = exp2f(accS[nt][3]);
                Zl[nt][0] += e0 + e2;
                Zl[nt][1] += e1 + e3;
                Rl[nt][0] += e0 * accQ[nt][0] + e2 * accQ[nt][2];
                Rl[nt][1] += e1 * accQ[nt][1] + e3 * accQ[nt][3];
                if (write_alpha) {
                    if (lab0 < Y_) {
                        float* rp = out_alpha + (arow0 + lab0) * L_;
                        rp[posA] = e0; rp[posB] = e2;
                    }
                    if (lab1 < Y_) {
                        float* rp = out_alpha + (arow0 + lab1) * L_;
                        rp[posA] = e1; rp[posB] = e3;
                    }
                }
            }
        }

        __syncthreads();      // readers done before buffer reuse at ch+2
    }
#undef STAGE

    // reduce over g (lane bits 2,3,4)
#pragma unroll
    for (int o = 4; o <= 16; o <<= 1) {
#pragma unroll
        for (int nt = 0; nt < 4; nt++) {
            Zl[nt][0] += __shfl_xor_sync(0xffffffffu, Zl[nt][0], o);
            Zl[nt][1] += __shfl_xor_sync(0xffffffffu, Zl[nt][1], o);
            Rl[nt][0] += __shfl_xor_sync(0xffffffffu, Rl[nt][0], o);
            Rl[nt][1] += __shfl_xor_sync(0xffffffffu, Rl[nt][1], o);
        }
    }
    if (lane < 4) {
#pragma unroll
        for (int nt = 0; nt < 4; nt++) {
            zs[warp * 32 + nt * 8 + 2 * lane + 0] = Zl[nt][0];
            zs[warp * 32 + nt * 8 + 2 * lane + 1] = Zl[nt][1];
            rs[warp * 32 + nt * 8 + 2 * lane + 0] = Rl[nt][0];
            rs[warp * 32 + nt * 8 + 2 * lane + 1] = Rl[nt][1];
        }
    }
    __syncthreads();

    // cross-warp combine + yhat + loss terms
    if (tid < YT) {
        float Z = 0.f, R = 0.f;
#pragma unroll
        for (int w = 0; w < 8; w++) { Z += zs[w * 32 + tid]; R += rs[w * 32 + tid]; }
        iZ_s[tid] = 1.f / Z;
        float lossterm = 0.f;
        int gy = y0t + tid;
        if (gy < Y_) {
            float r  = R / Z + final_b[gy];
            float yh = 1.f / (1.f + expf(-r));
            out_yhat[b * Y_ + gy] = yh;
            float tg = target[b * Y_ + gy];
            lossterm = tg * logf(yh + 1e-12f) + (1.f - tg) * logf(1.f - yh + 1e-12f);
        }
        lt[tid] = lossterm;
    }
    __syncthreads();
    if (tid == 0) {
        float s = 0.f;
#pragma unroll
        for (int i = 0; i < YT; i++) s += lt[i];
        g_losspart[b * gridDim.x + blockIdx.x] = s;
    }

    // in-place rescale (L2-hot). Alpha region sits at odd float offset:
    // element c==3 (mod 4) of each row is 16B-aligned -> scalar head (0,1,2) +
    // 511 float4 + scalar tail (2047).
    if (write_alpha) {
#pragma unroll
        for (int i = 0; i < 4; i++) {
            int yl = warp * 4 + i;
            int gy = y0t + yl;
            if (gy >= Y_) continue;
            float iZ = iZ_s[yl];
            float* ap = out_alpha + (arow0 + gy) * L_;
            if (lane == 0) { ap[0] *= iZ; ap[1] *= iZ; ap[2] *= iZ; ap[2047] *= iZ; }
            float4* v = (float4*)(ap + 3);
#pragma unroll 4
            for (int j = lane; j < 511; j += 32) {
                float4 x = v[j];
                x.x *= iZ; x.y *= iZ; x.z *= iZ; x.w *= iZ;
                v[j] = x;
            }
        }
    }
}

// ---------------------------------------------------------------------------
// Kernel 3: deterministic loss reduction
// ---------------------------------------------------------------------------
__global__ void loss_kernel(float* __restrict__ out_loss, int npart)
{
    __shared__ float red[256];
    float s = 0.f;
    for (int i = threadIdx.x; i < npart; i += 256) s += g_losspart[i];
    red[threadIdx.x] = s;
    __syncthreads();
    for (int o = 128; o > 0; o >>= 1) {
        if (threadIdx.x < o) red[threadIdx.x] += red[threadIdx.x + o];
        __syncthreads();
    }
    if (threadIdx.x == 0) *out_loss = -red[0] / (float)(B_ * Y_);
}

// ---------------------------------------------------------------------------
extern "C" void kernel_launch(void* const* d_in, const int* in_sizes, int n_in,
                              void* d_out, int out_size)
{
    const int*   tokens  = (const int*)  d_in[0];
    const float* target  = (const float*)d_in[1];
    const float* embed_W = (const float*)d_in[2];
    const float* conv_w  = (const float*)d_in[3];
    const float* conv_b  = (const float*)d_in[4];
    const float* U_w     = (const float*)d_in[5];
    const float* final_w = (const float*)d_in[6];
    const float* final_b = (const float*)d_in[7];
    float* out = (float*)d_out;

    const long long yhat_n  = (long long)B_ * Y_;                 // 71368
    const long long total_n = yhat_n + 1 + (long long)B_ * Y_ * L_;
    int write_loss  = (out_size >= (int)(yhat_n + 1)) ? 1 : 0;
    int write_alpha = ((long long)out_size >= total_n) ? 1 : 0;

    const int smem_bytes = (NKB * 4 * 32) * 16           // wS
                         + (NKB * 4 * 32) * 8            // wQ (hi only)
                         + 2 * 2 * (LCH * FPAIR) * 4     // hi/lo double buffers
                         + 2 * (LCH * 2) * 4             // h2 double buffer
                         + 32 * 16                       // w2
                         + (8 * 32 * 2 + YT + YT) * 4;   // zs, rs, iZ, lt
    cudaFuncSetAttribute(attn_kernel, cudaFuncAttributeMaxDynamicSharedMemorySize,
                         smem_bytes);

    conv_kernel<<<dim3(L_ / 32, B_), 256>>>(tokens, embed_W, conv_w, conv_b);

    float* out_alpha = out + yhat_n + 1;
    attn_kernel<<<dim3(NYT, B_), 256, smem_bytes>>>(
        U_w, final_w, final_b, target, out, out_alpha, write_alpha);

    if (write_loss)
        loss_kernel<<<1, 256>>>(out + yhat_n, B_ * NYT);
}